// round 15
// baseline (speedup 1.0000x reference)
#include <cuda_runtime.h>
#include <cuda_bf16.h>
#include <stdint.h>
#include <math.h>
#include <float.h>
#include <mma.h>

using namespace nvcuda;

#define Bsz 4
#define Npt 4096
#define KNN 20
#define EPSBN 1e-5f
#define NROWS (Bsz * Npt)
#define NGRP 512          // 8-col groups per row (contiguous: group g = cols g*8..g*8+7)
#define KG 21             // groups kept (top-20 + 1 tie guard)

// ---------------- scratch (device globals; no allocations) ----------------
__device__ float d_dist[(size_t)Bsz * Npt * Npt];   // 268 MB distance matrix
__device__ float d_g8[(size_t)NROWS * NGRP];        // per-row 8-col group maxes
__device__ float d_xcat[Bsz * 192 * Npt];           // x1|x2|x3 concatenated
__device__ float d_AC[Bsz * 128 * Npt];             // A (0:64) | Cc (64:128)
__device__ float d_y5[Bsz * 512 * Npt];
__device__ float d_y4[Bsz * 512 * Npt];
__device__ float d_y6[Bsz * 256 * Npt];
__device__ float d_y7[Bsz * 128 * Npt];
__device__ int   d_idx[Bsz * Npt * KNN];
__device__ float d_gmax[Bsz * 512];
__device__ float d_bias5[Bsz * 512];
__device__ float d_espart[64 * 8 * 2];   // edge-stats partials (s, s2)

__device__ __forceinline__ float lrelu(float v) { return v >= 0.f ? v : 0.2f * v; }

// order-preserving float->uint key (no NaNs in this data)
__device__ __forceinline__ unsigned fkey(float f) {
    unsigned u = __float_as_uint(f);
    return (u & 0x80000000u) ? ~u : (u | 0x80000000u);
}

// Kahan-compensated fp32 accumulator
__device__ __forceinline__ void kadd(float& s, float& c, float v) {
    float y = v - c;
    float t = s + y;
    c = (t - s) - y;
    s = t;
}

// ---------------- conv1: 3 -> 64 ----------------
__global__ void k_conv1(const float* __restrict__ x, const float* __restrict__ W1) {
    int n = blockIdx.x * 256 + threadIdx.x;
    int o = blockIdx.y, b = blockIdx.z;
    float v = W1[o * 3 + 0] * x[(b * 3 + 0) * Npt + n]
            + W1[o * 3 + 1] * x[(b * 3 + 1) * Npt + n]
            + W1[o * 3 + 2] * x[(b * 3 + 2) * Npt + n];
    d_xcat[((long)b * 192 + o) * Npt + n] = v;
}

// ---------------- fused BN stats + apply + lrelu (in place, fp32 Kahan) ----------------
__global__ void k_statsapply(float* __restrict__ buf, int CT, int c0,
                             const float* __restrict__ gamma, const float* __restrict__ beta) {
    int o = blockIdx.x;
    float s = 0.f, sc = 0.f, s2 = 0.f, s2c = 0.f;
    for (int i = threadIdx.x; i < Bsz * Npt; i += 256) {
        int b = i >> 12, n = i & (Npt - 1);
        float v = buf[((long)b * CT + c0 + o) * Npt + n];
        kadd(s, sc, v);
        kadd(s2, s2c, v * v);
    }
    __shared__ float sh[256], sh2[256];
    __shared__ float smv, srv;
    sh[threadIdx.x] = s; sh2[threadIdx.x] = s2; __syncthreads();
    for (int st = 128; st > 0; st >>= 1) {
        if (threadIdx.x < st) { sh[threadIdx.x] += sh[threadIdx.x + st]; sh2[threadIdx.x] += sh2[threadIdx.x + st]; }
        __syncthreads();
    }
    if (threadIdx.x == 0) {
        float cnt = (float)(Bsz * Npt);
        float m = sh[0] / cnt;
        float var = sh2[0] / cnt - m * m;
        smv = m;
        srv = rsqrtf(fmaxf(var, 0.f) + EPSBN);
    }
    __syncthreads();
    float m = smv, r = srv, g = gamma[o], be = beta[o];
    for (int i = threadIdx.x; i < Bsz * Npt; i += 256) {
        int b = i >> 12, n = i & (Npt - 1);
        long off = ((long)b * CT + c0 + o) * Npt + n;
        buf[off] = lrelu((buf[off] - m) * r * g + be);
    }
}

// ======== WMMA bf16 3-way-split symmetric distance GEMM (qs <= ns) ========
// a = a0+a1+a2 (24 mantissa bits). D = sum of 6 passes: A0B0+A0B1+A1B0+A1B1+A0B2+A2B0.
// Dropped terms ~3*2^-24 relative. Writes 2*dot - sq both halves + contiguous group maxes.
#define LDT 72
#define T_A0 0
#define T_A1 18432
#define T_A2 36864
#define T_B0 55296
#define T_B1 73728
#define T_B2 92160
#define OFF_SQN 110592
#define OFF_SQQ 111104
#define OFF_PB  111616
#define OFF_PA  112640
#define DW_SMEM 113664
#define LDS_ 132
__global__ void __launch_bounds__(256, 1) k_dist_wmma(int c0) {
    int ns = blockIdx.x, qs = blockIdx.y, b = blockIdx.z;
    if (ns < qs) return;
    extern __shared__ __align__(16) char smem[];
    int q0 = qs * 128, n0 = ns * 128;
    int t = threadIdx.x, w = t >> 5;

    __nv_bfloat16* tA0 = (__nv_bfloat16*)(smem + T_A0);
    __nv_bfloat16* tA1 = (__nv_bfloat16*)(smem + T_A1);
    __nv_bfloat16* tA2 = (__nv_bfloat16*)(smem + T_A2);
    __nv_bfloat16* tB0 = (__nv_bfloat16*)(smem + T_B0);
    __nv_bfloat16* tB1 = (__nv_bfloat16*)(smem + T_B1);
    __nv_bfloat16* tB2 = (__nv_bfloat16*)(smem + T_B2);
    float* partB = (float*)(smem + OFF_PB);
    float* partA = (float*)(smem + OFF_PA);

    // convert fp32 -> bf16 triple tiles [point][k], raw squared-norm partials
    const float* xb = d_xcat + ((long)b * 192 + c0) * Npt;
    {
        int nn = t & 127, kh = t >> 7;   // kh in {0,1}
        float ssqB = 0.f, ssqA = 0.f;
        #pragma unroll 4
        for (int it = 0; it < 32; it++) {
            int k = it * 2 + kh;
            int off = nn * LDT + k;
            float vb = xb[(long)k * Npt + n0 + nn];
            ssqB += vb * vb;
            __nv_bfloat16 b0 = __float2bfloat16(vb);
            float rb = vb - __bfloat162float(b0);
            __nv_bfloat16 b1 = __float2bfloat16(rb);
            float rb2 = rb - __bfloat162float(b1);
            tB0[off] = b0; tB1[off] = b1; tB2[off] = __float2bfloat16(rb2);
            float ra = xb[(long)k * Npt + q0 + nn];
            ssqA += ra * ra;
            float va = 2.f * ra;
            __nv_bfloat16 a0 = __float2bfloat16(va);
            float rra = va - __bfloat162float(a0);
            __nv_bfloat16 a1 = __float2bfloat16(rra);
            float rra2 = rra - __bfloat162float(a1);
            tA0[off] = a0; tA1[off] = a1; tA2[off] = __float2bfloat16(rra2);
        }
        partB[t] = ssqB;
        partA[t] = ssqA;
    }
    __syncthreads();
    float* sqN = (float*)(smem + OFF_SQN);
    float* sqQ = (float*)(smem + OFF_SQQ);
    if (t < 128) {
        sqN[t] = partB[t] + partB[t + 128];
        sqQ[t] = partA[t] + partA[t + 128];
    }
    __syncthreads();

    // MMA: warp w -> rows (w&3)*32..+31, cols (w>>2)*64..+63
    wmma::fragment<wmma::accumulator, 16, 16, 16, float> acc[2][4];
    #pragma unroll
    for (int i = 0; i < 2; i++)
        #pragma unroll
        for (int j = 0; j < 4; j++)
            wmma::fill_fragment(acc[i][j], 0.f);
    int row0 = (w & 3) * 32, col0 = (w >> 2) * 64;
    const __nv_bfloat16* Aps[6] = {tA0, tA0, tA1, tA1, tA0, tA2};
    const __nv_bfloat16* Bps[6] = {tB0, tB1, tB0, tB1, tB2, tB0};
    #pragma unroll
    for (int pass = 0; pass < 6; pass++) {
        const __nv_bfloat16* As = Aps[pass];
        const __nv_bfloat16* Bs = Bps[pass];
        #pragma unroll
        for (int kk = 0; kk < 64; kk += 16) {
            wmma::fragment<wmma::matrix_a, 16, 16, 16, __nv_bfloat16, wmma::row_major> fa0, fa1;
            wmma::load_matrix_sync(fa0, As + (row0 + 0) * LDT + kk, LDT);
            wmma::load_matrix_sync(fa1, As + (row0 + 16) * LDT + kk, LDT);
            #pragma unroll
            for (int cc = 0; cc < 4; cc++) {
                wmma::fragment<wmma::matrix_b, 16, 16, 16, __nv_bfloat16, wmma::col_major> fb;
                wmma::load_matrix_sync(fb, Bs + (col0 + cc * 16) * LDT + kk, LDT);
                wmma::mma_sync(acc[0][cc], fa0, fb, acc[0][cc]);
                wmma::mma_sync(acc[1][cc], fa1, fb, acc[1][cc]);
            }
        }
    }
    __syncthreads();   // all fragment loads done; tiles region can become stage

    float* stage = (float*)smem;   // [128][LDS_]
    #pragma unroll
    for (int i = 0; i < 2; i++)
        #pragma unroll
        for (int cc = 0; cc < 4; cc++)
            wmma::store_matrix_sync(&stage[(row0 + i * 16) * LDS_ + col0 + cc * 16],
                                    acc[i][cc], LDS_, wmma::mem_row_major);
    __syncthreads();

    long bN = (long)b * Npt;
    // normal half: rows q, cols n
    #pragma unroll 2
    for (int i = 0; i < 16; i++) {
        int idx = i * 1024 + t * 4;
        int row = idx >> 7, c = idx & 127;
        float4 v;
        v.x = stage[row * LDS_ + c + 0] - sqN[c + 0];
        v.y = stage[row * LDS_ + c + 1] - sqN[c + 1];
        v.z = stage[row * LDS_ + c + 2] - sqN[c + 2];
        v.w = stage[row * LDS_ + c + 3] - sqN[c + 3];
        *(float4*)&d_dist[(bN + q0 + row) * Npt + n0 + c] = v;
    }
    #pragma unroll 2
    for (int i = 0; i < 8; i++) {
        int gi = i * 256 + t;
        int row = gi >> 4, g = gi & 15;
        float m = -FLT_MAX;
        #pragma unroll
        for (int j = 0; j < 8; j++)
            m = fmaxf(m, stage[row * LDS_ + g * 8 + j] - sqN[g * 8 + j]);
        d_g8[(bN + q0 + row) * NGRP + ns * 16 + g] = m;
    }
    if (ns != qs) {
        #pragma unroll 2
        for (int i = 0; i < 16; i++) {
            int idx = i * 1024 + t * 4;
            int n = idx >> 7, q = idx & 127;
            float4 v;
            v.x = stage[(q + 0) * LDS_ + n] - sqQ[q + 0];
            v.y = stage[(q + 1) * LDS_ + n] - sqQ[q + 1];
            v.z = stage[(q + 2) * LDS_ + n] - sqQ[q + 2];
            v.w = stage[(q + 3) * LDS_ + n] - sqQ[q + 3];
            *(float4*)&d_dist[(bN + n0 + n) * Npt + q0 + q] = v;
        }
        #pragma unroll 2
        for (int i = 0; i < 8; i++) {
            int gi = i * 256 + t;
            int n = gi >> 4, g = gi & 15;
            float m = -FLT_MAX;
            #pragma unroll
            for (int j = 0; j < 8; j++)
                m = fmaxf(m, stage[(g * 8 + j) * LDS_ + n] - sqQ[g * 8 + j]);
            d_g8[(bN + n0 + n) * NGRP + qs * 16 + g] = m;
        }
    }
}

// ---------------- fused warp-per-row kNN select (redux.sync argmax) ----------------
// CONTIGUOUS group convention: group g covers columns g*8 .. g*8+7.
__global__ void k_knn_select() {
    int warp = threadIdx.x >> 5, lane = threadIdx.x & 31;
    int row = blockIdx.x * 8 + warp;
    const float* g = d_g8 + (long)row * NGRP;
    float v[16];
    #pragma unroll
    for (int j = 0; j < 16; j++) v[j] = g[lane + 32 * j];
    float lmax = v[0]; int lj = 0;
    #pragma unroll
    for (int j = 1; j < 16; j++) if (v[j] > lmax) { lmax = v[j]; lj = j; }
    unsigned lkey = fkey(lmax);
    int mygroup = 0;   // lane t holds the t-th selected group (t < KG)
    #pragma unroll 1
    for (int t = 0; t < KG; t++) {
        unsigned wkey = __reduce_max_sync(0xffffffffu, lkey);
        unsigned gid = (unsigned)(lane + 32 * lj);
        unsigned bidx = __reduce_min_sync(0xffffffffu, (lkey == wkey) ? gid : 0xffffffffu);
        if (lane == t) mygroup = (int)bidx;
        if (gid == bidx && lkey == wkey) {
            int s = (int)bidx >> 5;
            #pragma unroll
            for (int j = 0; j < 16; j++) if (j == s) v[j] = -FLT_MAX;
            lmax = v[0]; lj = 0;
            #pragma unroll
            for (int j = 1; j < 16; j++) if (v[j] > lmax) { lmax = v[j]; lj = j; }
            lkey = fkey(lmax);
        }
    }
    // gather phase: lanes 0..20 each own one group (8 contiguous candidates)
    const float* drow = d_dist + (long)row * Npt;
    float c[8];
    int base = 0;
    if (lane < KG) {
        base = mygroup * 8;
        float4 a = *(const float4*)&drow[base];
        float4 bb = *(const float4*)&drow[base + 4];
        c[0] = a.x;  c[1] = a.y;  c[2] = a.z;  c[3] = a.w;
        c[4] = bb.x; c[5] = bb.y; c[6] = bb.z; c[7] = bb.w;
    } else {
        #pragma unroll
        for (int j = 0; j < 8; j++) c[j] = -FLT_MAX;
    }
    float cmax = c[0]; int cj = 0;
    #pragma unroll
    for (int j = 1; j < 8; j++) if (c[j] > cmax) { cmax = c[j]; cj = j; }
    unsigned ckey = fkey(cmax);
    #pragma unroll 1
    for (int t = 0; t < KNN; t++) {
        unsigned lidx = (unsigned)(base + cj);
        unsigned wkey = __reduce_max_sync(0xffffffffu, ckey);
        unsigned bidx = __reduce_min_sync(0xffffffffu, (ckey == wkey) ? lidx : 0xffffffffu);
        if (lane == 0) d_idx[row * KNN + t] = (int)bidx;
        if (ckey == wkey && lidx == bidx) {
            #pragma unroll
            for (int j = 0; j < 8; j++) if (j == cj) c[j] = -FLT_MAX;
            cmax = c[0]; cj = 0;
            #pragma unroll
            for (int j = 1; j < 8; j++) if (c[j] > cmax) { cmax = c[j]; cj = j; }
            ckey = fkey(cmax);
        }
    }
}

// ======== 128x128 tile feature GEMM ========
__global__ void __launch_bounds__(256, 1) k_gemm128(
        float* __restrict__ out, const float* __restrict__ in,
        const float* __restrict__ W, const float* __restrict__ biasBO,
        int C, int ldw, int CTin, int c0in, int CTout, int c0out) {
    __shared__ float Ws[16][132];
    __shared__ float Xs[16][128];
    int b = blockIdx.z, o0 = blockIdx.y * 128, n0 = blockIdx.x * 128;
    int tid = threadIdx.x, tx = tid & 15, ty = tid >> 4;
    float acc[2][2][4][4] = {};
    const float* inB = in + ((long)b * CTin + c0in) * Npt + n0;
    #pragma unroll 1
    for (int ck = 0; ck < C; ck += 16) {
        #pragma unroll
        for (int r = 0; r < 8; r++) {
            int idx = r * 256 + tid;
            int oo = idx >> 4, cc = idx & 15;
            Ws[cc][oo] = W[(long)(o0 + oo) * ldw + ck + cc];
        }
        #pragma unroll
        for (int r = 0; r < 8; r++) {
            int idx = r * 256 + tid;
            int cc = idx >> 7, e = idx & 127;
            Xs[cc][e] = inB[(long)(ck + cc) * Npt + e];
        }
        __syncthreads();
        #pragma unroll
        for (int k = 0; k < 16; k++) {
            float4 a0 = *(const float4*)&Ws[k][ty * 4];
            float4 a1 = *(const float4*)&Ws[k][64 + ty * 4];
            float4 b0 = *(const float4*)&Xs[k][tx * 4];
            float4 b1 = *(const float4*)&Xs[k][64 + tx * 4];
            float aa[2][4] = {{a0.x, a0.y, a0.z, a0.w}, {a1.x, a1.y, a1.z, a1.w}};
            float bb[2][4] = {{b0.x, b0.y, b0.z, b0.w}, {b1.x, b1.y, b1.z, b1.w}};
            #pragma unroll
            for (int ii = 0; ii < 2; ii++)
                #pragma unroll
                for (int i = 0; i < 4; i++)
                    #pragma unroll
                    for (int jj = 0; jj < 2; jj++)
                        #pragma unroll
                        for (int j = 0; j < 4; j++)
                            acc[ii][jj][i][j] += aa[ii][i] * bb[jj][j];
        }
        __syncthreads();
    }
    #pragma unroll
    for (int ii = 0; ii < 2; ii++) {
        #pragma unroll
        for (int i = 0; i < 4; i++) {
            int o = o0 + ii * 64 + ty * 4 + i;
            float bias = biasBO ? biasBO[b * 512 + o] : 0.f;
            float* row = out + ((long)b * CTout + c0out + o) * Npt + n0;
            float4 v0, v1;
            v0.x = acc[ii][0][i][0] + bias; v0.y = acc[ii][0][i][1] + bias;
            v0.z = acc[ii][0][i][2] + bias; v0.w = acc[ii][0][i][3] + bias;
            v1.x = acc[ii][1][i][0] + bias; v1.y = acc[ii][1][i][1] + bias;
            v1.z = acc[ii][1][i][2] + bias; v1.w = acc[ii][1][i][3] + bias;
            *(float4*)&row[tx * 4] = v0;
            *(float4*)&row[64 + tx * 4] = v1;
        }
    }
}

// ======== edge-conv GEMM: output [A;C], weights transformed inline from W[128x128] ========
__global__ void __launch_bounds__(256, 1) k_gemm_edge(
        float* __restrict__ out, const float* __restrict__ in,
        const float* __restrict__ W, int c0in) {
    __shared__ float Ws[16][132];
    __shared__ float Xs[16][128];
    int b = blockIdx.z, n0 = blockIdx.x * 128;
    int tid = threadIdx.x, tx = tid & 15, ty = tid >> 4;
    float acc[2][2][4][4] = {};
    const float* inB = in + ((long)b * 192 + c0in) * Npt + n0;
    #pragma unroll 1
    for (int ck = 0; ck < 64; ck += 16) {
        #pragma unroll
        for (int r = 0; r < 8; r++) {
            int idx = r * 256 + tid;
            int oo = idx >> 4, cc = idx & 15;
            float w;
            if (oo < 64) {
                w = W[oo * 128 + ck + cc];
            } else {
                int o2 = oo - 64;
                w = W[o2 * 128 + 64 + ck + cc] - W[o2 * 128 + ck + cc];
            }
            Ws[cc][oo] = w;
        }
        #pragma unroll
        for (int r = 0; r < 8; r++) {
            int idx = r * 256 + tid;
            int cc = idx >> 7, e = idx & 127;
            Xs[cc][e] = inB[(long)(ck + cc) * Npt + e];
        }
        __syncthreads();
        #pragma unroll
        for (int k = 0; k < 16; k++) {
            float4 a0 = *(const float4*)&Ws[k][ty * 4];
            float4 a1 = *(const float4*)&Ws[k][64 + ty * 4];
            float4 b0 = *(const float4*)&Xs[k][tx * 4];
            float4 b1 = *(const float4*)&Xs[k][64 + tx * 4];
            float aa[2][4] = {{a0.x, a0.y, a0.z, a0.w}, {a1.x, a1.y, a1.z, a1.w}};
            float bb[2][4] = {{b0.x, b0.y, b0.z, b0.w}, {b1.x, b1.y, b1.z, b1.w}};
            #pragma unroll
            for (int ii = 0; ii < 2; ii++)
                #pragma unroll
                for (int i = 0; i < 4; i++)
                    #pragma unroll
                    for (int jj = 0; jj < 2; jj++)
                        #pragma unroll
                        for (int j = 0; j < 4; j++)
                            acc[ii][jj][i][j] += aa[ii][i] * bb[jj][j];
        }
        __syncthreads();
    }
    #pragma unroll
    for (int ii = 0; ii < 2; ii++) {
        #pragma unroll
        for (int i = 0; i < 4; i++) {
            int o = ii * 64 + ty * 4 + i;
            float* row = out + ((long)b * 128 + o) * Npt + n0;
            float4 v0 = make_float4(acc[ii][0][i][0], acc[ii][0][i][1], acc[ii][0][i][2], acc[ii][0][i][3]);
            float4 v1 = make_float4(acc[ii][1][i][0], acc[ii][1][i][1], acc[ii][1][i][2], acc[ii][1][i][3]);
            *(float4*)&row[tx * 4] = v0;
            *(float4*)&row[64 + tx * 4] = v1;
        }
    }
}

// ---------------- edge-conv BN stats: stage 1 (64 channels x 8 slices) ----------------
__global__ void k_edge_stats_part() {
    int o = blockIdx.x, slice = blockIdx.y;
    int tid = threadIdx.x;
    float s = 0.f, sc = 0.f, s2 = 0.f, s2c = 0.f;
    #pragma unroll 1
    for (int b = 0; b < Bsz; b++) {
        const float* Ab = d_AC + ((long)b * 128 + o) * Npt;
        const float* Cb = d_AC + ((long)b * 128 + 64 + o) * Npt;
        #pragma unroll 1
        for (int n = slice * 512 + tid; n < (slice + 1) * 512; n += 256) {
            float cc = Cb[n];
            const int* ip = d_idx + ((long)(b * Npt + n)) * KNN;
            #pragma unroll 4
            for (int k = 0; k < KNN; k++) {
                float v = Ab[ip[k]] + cc;
                kadd(s, sc, v);
                kadd(s2, s2c, v * v);
            }
        }
    }
    __shared__ float sh[256], sh2[256];
    sh[tid] = s; sh2[tid] = s2; __syncthreads();
    for (int st = 128; st > 0; st >>= 1) {
        if (tid < st) { sh[tid] += sh[tid + st]; sh2[tid] += sh2[tid + st]; }
        __syncthreads();
    }
    if (tid == 0) {
        d_espart[(o * 8 + slice) * 2 + 0] = sh[0];
        d_espart[(o * 8 + slice) * 2 + 1] = sh2[0];
    }
}

// ---------------- edge-conv BN+lrelu+max_k (finalize folded in) ----------------
__global__ void k_edge_apply(const float* __restrict__ gamma, const float* __restrict__ beta, int c0out) {
    int n = blockIdx.x * 256 + threadIdx.x, o = blockIdx.y, b = blockIdx.z;
    float s = 0.f, s2 = 0.f;
    #pragma unroll
    for (int p = 0; p < 8; p++) {
        s += d_espart[(o * 8 + p) * 2 + 0];
        s2 += d_espart[(o * 8 + p) * 2 + 1];
    }
    float cnt = (float)(Bsz * Npt * KNN);
    float m = s / cnt;
    float var = s2 / cnt - m * m;
    float r = rsqrtf(fmaxf(var, 0.f) + EPSBN);
    float g = gamma[o], be = beta[o];
    const float* Ab = d_AC + ((long)b * 128 + o) * Npt;
    float cc = d_AC[((long)b * 128 + 64 + o) * Npt + n];
    const int* ip = d_idx + (b * Npt + n) * KNN;
    float best = -FLT_MAX;
    #pragma unroll 4
    for (int k = 0; k < KNN; k++) {
        float v = Ab[ip[k]] + cc;
        v = lrelu((v - m) * r * g + be);
        best = fmaxf(best, v);
    }
    d_xcat[((long)b * 192 + c0out + o) * Npt + n] = best;
}

// ---------------- fused stats + BN + lrelu + max over n -> gmax (fp32 Kahan) ----------------
__global__ void k_stats_gmax(const float* __restrict__ buf,
                             const float* __restrict__ gamma, const float* __restrict__ beta) {
    int o = blockIdx.x;  // 512
    float s = 0.f, sc = 0.f, s2 = 0.f, s2c = 0.f;
    for (int i = threadIdx.x; i < Bsz * Npt; i += 256) {
        int b = i >> 12, n = i & (Npt - 1);
        float v = buf[((long)b * 512 + o) * Npt + n];
        kadd(s, sc, v);
        kadd(s2, s2c, v * v);
    }
    __shared__ float sh[256], sh2[256];
    __shared__ float smv, srv;
    sh[threadIdx.x] = s; sh2[threadIdx.x] = s2; __syncthreads();
    for (int st = 128; st > 0; st >>= 1) {
        if (threadIdx.x < st) { sh[threadIdx.x] += sh[threadIdx.x + st]; sh2[threadIdx.x] += sh2[threadIdx.x + st]; }
        __syncthreads();
    }
    if (threadIdx.x == 0) {
        float cnt = (float)(Bsz * Npt);
        float m = sh[0] / cnt;
        float var = sh2[0] / cnt - m * m;
        smv = m;
        srv = rsqrtf(fmaxf(var, 0.f) + EPSBN);
    }
    __syncthreads();
    float m = smv, r = srv, g = gamma[o], be = beta[o];
    __shared__ float shm[256];
    for (int b = 0; b < Bsz; b++) {
        float best = -FLT_MAX;
        for (int n = threadIdx.x; n < Npt; n += 256) {
            float v = buf[((long)b * 512 + o) * Npt + n];
            best = fmaxf(best, lrelu((v - m) * r * g + be));
        }
        shm[threadIdx.x] = best; __syncthreads();
        for (int st = 128; st > 0; st >>= 1) {
            if (threadIdx.x < st) shm[threadIdx.x] = fmaxf(shm[threadIdx.x], shm[threadIdx.x + st]);
            __syncthreads();
        }
        if (threadIdx.x == 0) d_gmax[b * 512 + o] = shm[0];
        __syncthreads();
    }
}

// ---------------- fold W5[:,192:] @ broadcast(gmax) into a per-(b,o) bias ----------------
__global__ void k_bias5(const float* __restrict__ W5) {
    int t = blockIdx.x * 128 + threadIdx.x;
    int b = t >> 9, o = t & 511;
    float s = 0.f;
    #pragma unroll 8
    for (int c = 0; c < 512; c++)
        s += W5[(long)o * 704 + 192 + c] * d_gmax[b * 512 + c];
    d_bias5[b * 512 + o] = s;
}

// ---------------- final conv 128 -> 2 + bias ----------------
__global__ void k_final(const float* __restrict__ W8, const float* __restrict__ b8,
                        float* __restrict__ out) {
    int n = blockIdx.x * 256 + threadIdx.x, b = blockIdx.y;
    float s0 = b8[0], s1 = b8[1];
    #pragma unroll 8
    for (int c = 0; c < 128; c++) {
        float h = d_y7[((long)b * 128 + c) * Npt + n];
        s0 += W8[c] * h;
        s1 += W8[128 + c] * h;
    }
    out[(b * 2 + 0) * Npt + n] = s0;
    out[(b * 2 + 1) * Npt + n] = s1;
}

// ---------------- host ----------------
extern "C" void kernel_launch(void* const* d_in, const int* in_sizes, int n_in,
                              void* d_out, int out_size) {
    (void)in_sizes; (void)n_in; (void)out_size;
    const float* x   = (const float*)d_in[0];
    const float* W1  = (const float*)d_in[1];
    const float* W2  = (const float*)d_in[2];
    const float* W3  = (const float*)d_in[3];
    const float* W4  = (const float*)d_in[4];
    const float* W5  = (const float*)d_in[5];
    const float* W6  = (const float*)d_in[6];
    const float* W7  = (const float*)d_in[7];
    const float* W8  = (const float*)d_in[8];
    const float* b8  = (const float*)d_in[9];
    const float* g1 = (const float*)d_in[10], *bb1 = (const float*)d_in[11];
    const float* g2 = (const float*)d_in[12], *bb2 = (const float*)d_in[13];
    const float* g3 = (const float*)d_in[14], *bb3 = (const float*)d_in[15];
    const float* g4 = (const float*)d_in[16], *bb4 = (const float*)d_in[17];
    const float* g5 = (const float*)d_in[18], *bb5 = (const float*)d_in[19];
    const float* g6 = (const float*)d_in[20], *bb6 = (const float*)d_in[21];
    const float* g7 = (const float*)d_in[22], *bb7 = (const float*)d_in[23];

    static int smem_set = 0;
    if (!smem_set) {
        cudaFuncSetAttribute(k_dist_wmma, cudaFuncAttributeMaxDynamicSharedMemorySize, DW_SMEM);
        smem_set = 1;
    }

    void *pv;
    cudaGetSymbolAddress(&pv, d_xcat);  float* p_xcat = (float*)pv;
    cudaGetSymbolAddress(&pv, d_AC);    float* p_AC   = (float*)pv;
    cudaGetSymbolAddress(&pv, d_y4);    float* p_y4   = (float*)pv;
    cudaGetSymbolAddress(&pv, d_y5);    float* p_y5   = (float*)pv;
    cudaGetSymbolAddress(&pv, d_y6);    float* p_y6   = (float*)pv;
    cudaGetSymbolAddress(&pv, d_y7);    float* p_y7   = (float*)pv;
    cudaGetSymbolAddress(&pv, d_bias5); float* p_b5   = (float*)pv;

    // conv1 + BN + lrelu -> x1 (xcat[0:64))
    k_conv1<<<dim3(16, 64, 4), 256>>>(x, W1);
    k_statsapply<<<64, 256>>>(p_xcat, 192, 0, g1, bb1);

    // kNN round 1 on x1: WMMA 3-way-split symmetric dist + group max -> fused select
    k_dist_wmma<<<dim3(32, 32, 4), 256, DW_SMEM>>>(0);
    k_knn_select<<<2048, 256>>>();

    // edge-conv 2 -> x2 (xcat[64:128))
    k_gemm_edge<<<dim3(32, 1, 4), 256>>>(p_AC, p_xcat, W2, 0);
    k_edge_stats_part<<<dim3(64, 8), 256>>>();
    k_edge_apply<<<dim3(16, 64, 4), 256>>>(g2, bb2, 64);

    // kNN round 2 on x2
    k_dist_wmma<<<dim3(32, 32, 4), 256, DW_SMEM>>>(64);
    k_knn_select<<<2048, 256>>>();

    // edge-conv 3 -> x3 (xcat[128:192))
    k_gemm_edge<<<dim3(32, 1, 4), 256>>>(p_AC, p_xcat, W3, 64);
    k_edge_stats_part<<<dim3(64, 8), 256>>>();
    k_edge_apply<<<dim3(16, 64, 4), 256>>>(g3, bb3, 128);

    // global branch: y4 = W4 @ x3; fused stats+BN+lrelu+max -> gmax; fold into bias5
    k_gemm128<<<dim3(32, 4, 4), 256>>>(p_y4, p_xcat, W4, nullptr, 64, 64, 192, 128, 512, 0);
    k_stats_gmax<<<512, 256>>>(p_y4, g4, bb4);
    k_bias5<<<16, 128>>>(W5);

    // W5 on [x1;x2;x3] (C=192) + bias5; BN; lrelu
    k_gemm128<<<dim3(32, 4, 4), 256>>>(p_y5, p_xcat, W5, p_b5, 192, 704, 192, 0, 512, 0);
    k_statsapply<<<512, 256>>>(p_y5, 512, 0, g5, bb5);

    // W6
    k_gemm128<<<dim3(32, 2, 4), 256>>>(p_y6, p_y5, W6, nullptr, 512, 512, 512, 0, 256, 0);
    k_statsapply<<<256, 256>>>(p_y6, 256, 0, g6, bb6);

    // W7
    k_gemm128<<<dim3(32, 1, 4), 256>>>(p_y7, p_y6, W7, nullptr, 256, 256, 256, 0, 128, 0);
    k_statsapply<<<128, 256>>>(p_y7, 128, 0, g7, bb7);

    // final 128 -> 2
    k_final<<<dim3(16, 4), 256>>>(W8, b8, (float*)d_out);
}

// round 16
// speedup vs baseline: 1.2539x; 1.2539x over previous
#include <cuda_runtime.h>
#include <stdint.h>
#include <math.h>
#include <float.h>

#define Bsz 4
#define Npt 4096
#define KNN 20
#define EPSBN 1e-5f
#define NROWS (Bsz * Npt)
#define NGRP 512          // 8-col groups per row (interleaved: group (t) = cols t*4..+3 and 64+t*4..+3 within 128-tile)
#define KG 21             // groups kept (top-20 + 1 tie guard)

typedef unsigned long long u64;

// ---------------- scratch (device globals; no allocations) ----------------
__device__ float d_dist[(size_t)Bsz * Npt * Npt];   // 268 MB distance matrix
__device__ float d_g8[(size_t)NROWS * NGRP];        // per-row 8-col group maxes
__device__ float d_xcat[Bsz * 192 * Npt];           // x1|x2|x3 concatenated
__device__ float d_AC[Bsz * 128 * Npt];             // A (0:64) | Cc (64:128)
__device__ float d_y5[Bsz * 512 * Npt];
__device__ float d_y4[Bsz * 512 * Npt];
__device__ float d_y6[Bsz * 256 * Npt];
__device__ float d_y7[Bsz * 128 * Npt];
__device__ int   d_idx[Bsz * Npt * KNN];
__device__ float d_gmax[Bsz * 512];
__device__ float d_bias5[Bsz * 512];
__device__ float d_espart[64 * 8 * 2];   // edge-stats partials (s, s2)

__device__ __forceinline__ float lrelu(float v) { return v >= 0.f ? v : 0.2f * v; }

// order-preserving float->uint key (no NaNs in this data)
__device__ __forceinline__ unsigned fkey(float f) {
    unsigned u = __float_as_uint(f);
    return (u & 0x80000000u) ? ~u : (u | 0x80000000u);
}

// Kahan-compensated fp32 accumulator
__device__ __forceinline__ void kadd(float& s, float& c, float v) {
    float y = v - c;
    float t = s + y;
    c = (t - s) - y;
    s = t;
}

// ---- packed f32x2 helpers (sm_10x FFMA2) ----
__device__ __forceinline__ u64 dup2(float a) {
    u64 r;
    asm("mov.b64 %0, {%1, %1};" : "=l"(r) : "r"(__float_as_uint(a)));
    return r;
}
__device__ __forceinline__ void fma2(u64& d, u64 a, u64 b) {
    asm("fma.rn.f32x2 %0, %1, %2, %0;" : "+l"(d) : "l"(a), "l"(b));
}
__device__ __forceinline__ void unpack2(u64 p, float& lo, float& hi) {
    unsigned a, b;
    asm("mov.b64 {%0, %1}, %2;" : "=r"(a), "=r"(b) : "l"(p));
    lo = __uint_as_float(a); hi = __uint_as_float(b);
}

// ---------------- conv1: 3 -> 64 ----------------
__global__ void k_conv1(const float* __restrict__ x, const float* __restrict__ W1) {
    int n = blockIdx.x * 256 + threadIdx.x;
    int o = blockIdx.y, b = blockIdx.z;
    float v = W1[o * 3 + 0] * x[(b * 3 + 0) * Npt + n]
            + W1[o * 3 + 1] * x[(b * 3 + 1) * Npt + n]
            + W1[o * 3 + 2] * x[(b * 3 + 2) * Npt + n];
    d_xcat[((long)b * 192 + o) * Npt + n] = v;
}

// ---------------- fused BN stats + apply + lrelu (in place, fp32 Kahan) ----------------
__global__ void k_statsapply(float* __restrict__ buf, int CT, int c0,
                             const float* __restrict__ gamma, const float* __restrict__ beta) {
    int o = blockIdx.x;
    float s = 0.f, sc = 0.f, s2 = 0.f, s2c = 0.f;
    for (int i = threadIdx.x; i < Bsz * Npt; i += 256) {
        int b = i >> 12, n = i & (Npt - 1);
        float v = buf[((long)b * CT + c0 + o) * Npt + n];
        kadd(s, sc, v);
        kadd(s2, s2c, v * v);
    }
    __shared__ float sh[256], sh2[256];
    __shared__ float smv, srv;
    sh[threadIdx.x] = s; sh2[threadIdx.x] = s2; __syncthreads();
    for (int st = 128; st > 0; st >>= 1) {
        if (threadIdx.x < st) { sh[threadIdx.x] += sh[threadIdx.x + st]; sh2[threadIdx.x] += sh2[threadIdx.x + st]; }
        __syncthreads();
    }
    if (threadIdx.x == 0) {
        float cnt = (float)(Bsz * Npt);
        float m = sh[0] / cnt;
        float var = sh2[0] / cnt - m * m;
        smv = m;
        srv = rsqrtf(fmaxf(var, 0.f) + EPSBN);
    }
    __syncthreads();
    float m = smv, r = srv, g = gamma[o], be = beta[o];
    for (int i = threadIdx.x; i < Bsz * Npt; i += 256) {
        int b = i >> 12, n = i & (Npt - 1);
        long off = ((long)b * CT + c0 + o) * Npt + n;
        buf[off] = lrelu((buf[off] - m) * r * g + be);
    }
}

// ======== symmetric 128x128 tile distance GEMM (qs <= ns only), f32x2 FMAs ========
__global__ void __launch_bounds__(256, 1) k_dist_sym(int c0) {
    int ns = blockIdx.x, qs = blockIdx.y, b = blockIdx.z;
    if (ns < qs) return;
    __shared__ float Qs[16][132];
    __shared__ float Ms[16][132];
    __shared__ float sqQ[128], sqM[128];
    int q0 = qs * 128, n0 = ns * 128;
    int tid = threadIdx.x, tx = tid & 15, ty = tid >> 4;
    u64 accp[2][2][4][2];
    #pragma unroll
    for (int ii = 0; ii < 2; ii++)
        #pragma unroll
        for (int jj = 0; jj < 2; jj++)
            #pragma unroll
            for (int i = 0; i < 4; i++)
                #pragma unroll
                for (int jp = 0; jp < 2; jp++)
                    accp[ii][jj][i][jp] = 0ull;
    float myssq = 0.f;
    const float* xb = d_xcat + ((long)b * 192 + c0) * Npt;
    #pragma unroll 1
    for (int ck = 0; ck < 64; ck += 16) {
        #pragma unroll
        for (int r = 0; r < 8; r++) {
            int idx = r * 256 + tid;
            int cc = idx >> 7, e = idx & 127;
            long rowoff = (long)(ck + cc) * Npt;
            Qs[cc][e] = xb[rowoff + q0 + e];
            Ms[cc][e] = xb[rowoff + n0 + e];
        }
        __syncthreads();
        if (tid < 128) {
            #pragma unroll
            for (int cc = 0; cc < 16; cc++) {
                float v = Ms[cc][tid];
                myssq += v * v;
            }
        } else {
            int t2 = tid - 128;
            #pragma unroll
            for (int cc = 0; cc < 16; cc++) {
                float v = Qs[cc][t2];
                myssq += v * v;
            }
        }
        #pragma unroll
        for (int k = 0; k < 16; k++) {
            float4 a0 = *(const float4*)&Qs[k][ty * 4];
            float4 a1 = *(const float4*)&Qs[k][64 + ty * 4];
            float4 b0 = *(const float4*)&Ms[k][tx * 4];
            float4 b1 = *(const float4*)&Ms[k][64 + tx * 4];
            u64 bp[2][2];
            bp[0][0] = ((const u64*)&b0)[0];
            bp[0][1] = ((const u64*)&b0)[1];
            bp[1][0] = ((const u64*)&b1)[0];
            bp[1][1] = ((const u64*)&b1)[1];
            float aa[2][4] = {{a0.x, a0.y, a0.z, a0.w}, {a1.x, a1.y, a1.z, a1.w}};
            #pragma unroll
            for (int ii = 0; ii < 2; ii++)
                #pragma unroll
                for (int i = 0; i < 4; i++) {
                    u64 ad = dup2(aa[ii][i]);
                    #pragma unroll
                    for (int jj = 0; jj < 2; jj++)
                        #pragma unroll
                        for (int jp = 0; jp < 2; jp++)
                            fma2(accp[ii][jj][i][jp], ad, bp[jj][jp]);
                }
        }
        __syncthreads();
    }
    // unpack accumulators
    float acc[2][2][4][4];
    #pragma unroll
    for (int ii = 0; ii < 2; ii++)
        #pragma unroll
        for (int jj = 0; jj < 2; jj++)
            #pragma unroll
            for (int i = 0; i < 4; i++)
                #pragma unroll
                for (int jp = 0; jp < 2; jp++)
                    unpack2(accp[ii][jj][i][jp], acc[ii][jj][i][jp * 2], acc[ii][jj][i][jp * 2 + 1]);

    if (tid < 128) sqM[tid] = myssq; else sqQ[tid - 128] = myssq;
    __syncthreads();
    long bN = (long)b * Npt;
    // -------- normal block: rows q, cols n --------
    {
        float sn0[4], sn1[4];
        #pragma unroll
        for (int j = 0; j < 4; j++) {
            sn0[j] = sqM[tx * 4 + j];
            sn1[j] = sqM[64 + tx * 4 + j];
        }
        #pragma unroll
        for (int ii = 0; ii < 2; ii++) {
            #pragma unroll
            for (int i = 0; i < 4; i++) {
                int q = q0 + ii * 64 + ty * 4 + i;
                float* row = d_dist + (bN + q) * Npt + n0;
                float4 v0, v1;
                v0.x = 2.f * acc[ii][0][i][0] - sn0[0];
                v0.y = 2.f * acc[ii][0][i][1] - sn0[1];
                v0.z = 2.f * acc[ii][0][i][2] - sn0[2];
                v0.w = 2.f * acc[ii][0][i][3] - sn0[3];
                v1.x = 2.f * acc[ii][1][i][0] - sn1[0];
                v1.y = 2.f * acc[ii][1][i][1] - sn1[1];
                v1.z = 2.f * acc[ii][1][i][2] - sn1[2];
                v1.w = 2.f * acc[ii][1][i][3] - sn1[3];
                *(float4*)&row[tx * 4] = v0;
                *(float4*)&row[64 + tx * 4] = v1;
                float m01 = fmaxf(fmaxf(v0.x, v0.y), fmaxf(v0.z, v0.w));
                float m23 = fmaxf(fmaxf(v1.x, v1.y), fmaxf(v1.z, v1.w));
                d_g8[(bN + q) * NGRP + ns * 16 + tx] = fmaxf(m01, m23);
            }
        }
    }
    // -------- transposed block: rows n, cols q (skip on diagonal) --------
    if (ns != qs) {
        float sq0[4], sq1[4];
        #pragma unroll
        for (int i = 0; i < 4; i++) {
            sq0[i] = sqQ[ty * 4 + i];
            sq1[i] = sqQ[64 + ty * 4 + i];
        }
        #pragma unroll
        for (int jj = 0; jj < 2; jj++) {
            #pragma unroll
            for (int j = 0; j < 4; j++) {
                int n = n0 + jj * 64 + tx * 4 + j;
                float* row = d_dist + (bN + n) * Npt;
                float4 w0, w1;
                w0.x = 2.f * acc[0][jj][0][j] - sq0[0];
                w0.y = 2.f * acc[0][jj][1][j] - sq0[1];
                w0.z = 2.f * acc[0][jj][2][j] - sq0[2];
                w0.w = 2.f * acc[0][jj][3][j] - sq0[3];
                w1.x = 2.f * acc[1][jj][0][j] - sq1[0];
                w1.y = 2.f * acc[1][jj][1][j] - sq1[1];
                w1.z = 2.f * acc[1][jj][2][j] - sq1[2];
                w1.w = 2.f * acc[1][jj][3][j] - sq1[3];
                *(float4*)&row[q0 + ty * 4] = w0;
                *(float4*)&row[q0 + 64 + ty * 4] = w1;
                float m01 = fmaxf(fmaxf(w0.x, w0.y), fmaxf(w0.z, w0.w));
                float m23 = fmaxf(fmaxf(w1.x, w1.y), fmaxf(w1.z, w1.w));
                d_g8[(bN + n) * NGRP + qs * 16 + ty] = fmaxf(m01, m23);
            }
        }
    }
}

// ---------------- fused warp-per-row kNN select (redux.sync argmax) ----------------
// INTERLEAVED group convention (matches dist_sym epilogue).
__global__ void k_knn_select() {
    int warp = threadIdx.x >> 5, lane = threadIdx.x & 31;
    int row = blockIdx.x * 8 + warp;
    const float* g = d_g8 + (long)row * NGRP;
    float v[16];
    #pragma unroll
    for (int j = 0; j < 16; j++) v[j] = g[lane + 32 * j];
    float lmax = v[0]; int lj = 0;
    #pragma unroll
    for (int j = 1; j < 16; j++) if (v[j] > lmax) { lmax = v[j]; lj = j; }
    unsigned lkey = fkey(lmax);
    int mygroup = 0;   // lane t holds the t-th selected group (t < KG)
    #pragma unroll 1
    for (int t = 0; t < KG; t++) {
        unsigned wkey = __reduce_max_sync(0xffffffffu, lkey);
        unsigned gid = (unsigned)(lane + 32 * lj);
        unsigned bidx = __reduce_min_sync(0xffffffffu, (lkey == wkey) ? gid : 0xffffffffu);
        if (lane == t) mygroup = (int)bidx;
        if (gid == bidx && lkey == wkey) {
            int s = (int)bidx >> 5;
            #pragma unroll
            for (int j = 0; j < 16; j++) if (j == s) v[j] = -FLT_MAX;
            lmax = v[0]; lj = 0;
            #pragma unroll
            for (int j = 1; j < 16; j++) if (v[j] > lmax) { lmax = v[j]; lj = j; }
            lkey = fkey(lmax);
        }
    }
    // gather phase: lanes 0..20 each own one group (8 candidates, interleaved halves)
    const float* drow = d_dist + (long)row * Npt;
    float c[8];
    int base = 0;
    if (lane < KG) {
        base = (mygroup >> 4) * 128 + (mygroup & 15) * 4;
        float4 a = *(const float4*)&drow[base];
        float4 bb = *(const float4*)&drow[base + 64];
        c[0] = a.x;  c[1] = a.y;  c[2] = a.z;  c[3] = a.w;
        c[4] = bb.x; c[5] = bb.y; c[6] = bb.z; c[7] = bb.w;
    } else {
        #pragma unroll
        for (int j = 0; j < 8; j++) c[j] = -FLT_MAX;
    }
    float cmax = c[0]; int cj = 0;
    #pragma unroll
    for (int j = 1; j < 8; j++) if (c[j] > cmax) { cmax = c[j]; cj = j; }
    unsigned ckey = fkey(cmax);
    #pragma unroll 1
    for (int t = 0; t < KNN; t++) {
        unsigned lidx = (unsigned)(base + (cj < 4 ? cj : 60 + cj));
        unsigned wkey = __reduce_max_sync(0xffffffffu, ckey);
        unsigned bidx = __reduce_min_sync(0xffffffffu, (ckey == wkey) ? lidx : 0xffffffffu);
        if (lane == 0) d_idx[row * KNN + t] = (int)bidx;
        if (ckey == wkey && lidx == bidx) {
            #pragma unroll
            for (int j = 0; j < 8; j++) if (j == cj) c[j] = -FLT_MAX;
            cmax = c[0]; cj = 0;
            #pragma unroll
            for (int j = 1; j < 8; j++) if (c[j] > cmax) { cmax = c[j]; cj = j; }
            ckey = fkey(cmax);
        }
    }
}

// ======== 128x128 tile feature GEMM, f32x2 FMAs ========
__global__ void __launch_bounds__(256, 1) k_gemm128(
        float* __restrict__ out, const float* __restrict__ in,
        const float* __restrict__ W, const float* __restrict__ biasBO,
        int C, int ldw, int CTin, int c0in, int CTout, int c0out) {
    __shared__ float Ws[16][132];
    __shared__ float Xs[16][128];
    int b = blockIdx.z, o0 = blockIdx.y * 128, n0 = blockIdx.x * 128;
    int tid = threadIdx.x, tx = tid & 15, ty = tid >> 4;
    u64 accp[2][2][4][2];
    #pragma unroll
    for (int ii = 0; ii < 2; ii++)
        #pragma unroll
        for (int jj = 0; jj < 2; jj++)
            #pragma unroll
            for (int i = 0; i < 4; i++)
                #pragma unroll
                for (int jp = 0; jp < 2; jp++)
                    accp[ii][jj][i][jp] = 0ull;
    const float* inB = in + ((long)b * CTin + c0in) * Npt + n0;
    #pragma unroll 1
    for (int ck = 0; ck < C; ck += 16) {
        #pragma unroll
        for (int r = 0; r < 8; r++) {
            int idx = r * 256 + tid;
            int oo = idx >> 4, cc = idx & 15;
            Ws[cc][oo] = W[(long)(o0 + oo) * ldw + ck + cc];
        }
        #pragma unroll
        for (int r = 0; r < 8; r++) {
            int idx = r * 256 + tid;
            int cc = idx >> 7, e = idx & 127;
            Xs[cc][e] = inB[(long)(ck + cc) * Npt + e];
        }
        __syncthreads();
        #pragma unroll
        for (int k = 0; k < 16; k++) {
            float4 a0 = *(const float4*)&Ws[k][ty * 4];
            float4 a1 = *(const float4*)&Ws[k][64 + ty * 4];
            float4 b0 = *(const float4*)&Xs[k][tx * 4];
            float4 b1 = *(const float4*)&Xs[k][64 + tx * 4];
            u64 bp[2][2];
            bp[0][0] = ((const u64*)&b0)[0];
            bp[0][1] = ((const u64*)&b0)[1];
            bp[1][0] = ((const u64*)&b1)[0];
            bp[1][1] = ((const u64*)&b1)[1];
            float aa[2][4] = {{a0.x, a0.y, a0.z, a0.w}, {a1.x, a1.y, a1.z, a1.w}};
            #pragma unroll
            for (int ii = 0; ii < 2; ii++)
                #pragma unroll
                for (int i = 0; i < 4; i++) {
                    u64 ad = dup2(aa[ii][i]);
                    #pragma unroll
                    for (int jj = 0; jj < 2; jj++)
                        #pragma unroll
                        for (int jp = 0; jp < 2; jp++)
                            fma2(accp[ii][jj][i][jp], ad, bp[jj][jp]);
                }
        }
        __syncthreads();
    }
    float acc[2][2][4][4];
    #pragma unroll
    for (int ii = 0; ii < 2; ii++)
        #pragma unroll
        for (int jj = 0; jj < 2; jj++)
            #pragma unroll
            for (int i = 0; i < 4; i++)
                #pragma unroll
                for (int jp = 0; jp < 2; jp++)
                    unpack2(accp[ii][jj][i][jp], acc[ii][jj][i][jp * 2], acc[ii][jj][i][jp * 2 + 1]);
    #pragma unroll
    for (int ii = 0; ii < 2; ii++) {
        #pragma unroll
        for (int i = 0; i < 4; i++) {
            int o = o0 + ii * 64 + ty * 4 + i;
            float bias = biasBO ? biasBO[b * 512 + o] : 0.f;
            float* row = out + ((long)b * CTout + c0out + o) * Npt + n0;
            float4 v0, v1;
            v0.x = acc[ii][0][i][0] + bias; v0.y = acc[ii][0][i][1] + bias;
            v0.z = acc[ii][0][i][2] + bias; v0.w = acc[ii][0][i][3] + bias;
            v1.x = acc[ii][1][i][0] + bias; v1.y = acc[ii][1][i][1] + bias;
            v1.z = acc[ii][1][i][2] + bias; v1.w = acc[ii][1][i][3] + bias;
            *(float4*)&row[tx * 4] = v0;
            *(float4*)&row[64 + tx * 4] = v1;
        }
    }
}

// ======== edge-conv GEMM: output [A;C], weights transformed inline, f32x2 FMAs ========
__global__ void __launch_bounds__(256, 1) k_gemm_edge(
        float* __restrict__ out, const float* __restrict__ in,
        const float* __restrict__ W, int c0in) {
    __shared__ float Ws[16][132];
    __shared__ float Xs[16][128];
    int b = blockIdx.z, n0 = blockIdx.x * 128;
    int tid = threadIdx.x, tx = tid & 15, ty = tid >> 4;
    u64 accp[2][2][4][2];
    #pragma unroll
    for (int ii = 0; ii < 2; ii++)
        #pragma unroll
        for (int jj = 0; jj < 2; jj++)
            #pragma unroll
            for (int i = 0; i < 4; i++)
                #pragma unroll
                for (int jp = 0; jp < 2; jp++)
                    accp[ii][jj][i][jp] = 0ull;
    const float* inB = in + ((long)b * 192 + c0in) * Npt + n0;
    #pragma unroll 1
    for (int ck = 0; ck < 64; ck += 16) {
        #pragma unroll
        for (int r = 0; r < 8; r++) {
            int idx = r * 256 + tid;
            int oo = idx >> 4, cc = idx & 15;
            float w;
            if (oo < 64) {
                w = W[oo * 128 + ck + cc];
            } else {
                int o2 = oo - 64;
                w = W[o2 * 128 + 64 + ck + cc] - W[o2 * 128 + ck + cc];
            }
            Ws[cc][oo] = w;
        }
        #pragma unroll
        for (int r = 0; r < 8; r++) {
            int idx = r * 256 + tid;
            int cc = idx >> 7, e = idx & 127;
            Xs[cc][e] = inB[(long)(ck + cc) * Npt + e];
        }
        __syncthreads();
        #pragma unroll
        for (int k = 0; k < 16; k++) {
            float4 a0 = *(const float4*)&Ws[k][ty * 4];
            float4 a1 = *(const float4*)&Ws[k][64 + ty * 4];
            float4 b0 = *(const float4*)&Xs[k][tx * 4];
            float4 b1 = *(const float4*)&Xs[k][64 + tx * 4];
            u64 bp[2][2];
            bp[0][0] = ((const u64*)&b0)[0];
            bp[0][1] = ((const u64*)&b0)[1];
            bp[1][0] = ((const u64*)&b1)[0];
            bp[1][1] = ((const u64*)&b1)[1];
            float aa[2][4] = {{a0.x, a0.y, a0.z, a0.w}, {a1.x, a1.y, a1.z, a1.w}};
            #pragma unroll
            for (int ii = 0; ii < 2; ii++)
                #pragma unroll
                for (int i = 0; i < 4; i++) {
                    u64 ad = dup2(aa[ii][i]);
                    #pragma unroll
                    for (int jj = 0; jj < 2; jj++)
                        #pragma unroll
                        for (int jp = 0; jp < 2; jp++)
                            fma2(accp[ii][jj][i][jp], ad, bp[jj][jp]);
                }
        }
        __syncthreads();
    }
    float acc[2][2][4][4];
    #pragma unroll
    for (int ii = 0; ii < 2; ii++)
        #pragma unroll
        for (int jj = 0; jj < 2; jj++)
            #pragma unroll
            for (int i = 0; i < 4; i++)
                #pragma unroll
                for (int jp = 0; jp < 2; jp++)
                    unpack2(accp[ii][jj][i][jp], acc[ii][jj][i][jp * 2], acc[ii][jj][i][jp * 2 + 1]);
    #pragma unroll
    for (int ii = 0; ii < 2; ii++) {
        #pragma unroll
        for (int i = 0; i < 4; i++) {
            int o = ii * 64 + ty * 4 + i;
            float* row = out + ((long)b * 128 + o) * Npt + n0;
            float4 v0 = make_float4(acc[ii][0][i][0], acc[ii][0][i][1], acc[ii][0][i][2], acc[ii][0][i][3]);
            float4 v1 = make_float4(acc[ii][1][i][0], acc[ii][1][i][1], acc[ii][1][i][2], acc[ii][1][i][3]);
            *(float4*)&row[tx * 4] = v0;
            *(float4*)&row[64 + tx * 4] = v1;
        }
    }
}

// ---------------- edge-conv BN stats: stage 1 (64 channels x 8 slices) ----------------
__global__ void k_edge_stats_part() {
    int o = blockIdx.x, slice = blockIdx.y;
    int tid = threadIdx.x;
    float s = 0.f, sc = 0.f, s2 = 0.f, s2c = 0.f;
    #pragma unroll 1
    for (int b = 0; b < Bsz; b++) {
        const float* Ab = d_AC + ((long)b * 128 + o) * Npt;
        const float* Cb = d_AC + ((long)b * 128 + 64 + o) * Npt;
        #pragma unroll 1
        for (int n = slice * 512 + tid; n < (slice + 1) * 512; n += 256) {
            float cc = Cb[n];
            const int* ip = d_idx + ((long)(b * Npt + n)) * KNN;
            #pragma unroll 4
            for (int k = 0; k < KNN; k++) {
                float v = Ab[ip[k]] + cc;
                kadd(s, sc, v);
                kadd(s2, s2c, v * v);
            }
        }
    }
    __shared__ float sh[256], sh2[256];
    sh[tid] = s; sh2[tid] = s2; __syncthreads();
    for (int st = 128; st > 0; st >>= 1) {
        if (tid < st) { sh[tid] += sh[tid + st]; sh2[tid] += sh2[tid + st]; }
        __syncthreads();
    }
    if (tid == 0) {
        d_espart[(o * 8 + slice) * 2 + 0] = sh[0];
        d_espart[(o * 8 + slice) * 2 + 1] = sh2[0];
    }
}

// ---------------- edge-conv BN+lrelu+max_k (finalize folded in) ----------------
__global__ void k_edge_apply(const float* __restrict__ gamma, const float* __restrict__ beta, int c0out) {
    int n = blockIdx.x * 256 + threadIdx.x, o = blockIdx.y, b = blockIdx.z;
    float s = 0.f, s2 = 0.f;
    #pragma unroll
    for (int p = 0; p < 8; p++) {
        s += d_espart[(o * 8 + p) * 2 + 0];
        s2 += d_espart[(o * 8 + p) * 2 + 1];
    }
    float cnt = (float)(Bsz * Npt * KNN);
    float m = s / cnt;
    float var = s2 / cnt - m * m;
    float r = rsqrtf(fmaxf(var, 0.f) + EPSBN);
    float g = gamma[o], be = beta[o];
    const float* Ab = d_AC + ((long)b * 128 + o) * Npt;
    float cc = d_AC[((long)b * 128 + 64 + o) * Npt + n];
    const int* ip = d_idx + (b * Npt + n) * KNN;
    float best = -FLT_MAX;
    #pragma unroll 4
    for (int k = 0; k < KNN; k++) {
        float v = Ab[ip[k]] + cc;
        v = lrelu((v - m) * r * g + be);
        best = fmaxf(best, v);
    }
    d_xcat[((long)b * 192 + c0out + o) * Npt + n] = best;
}

// ---------------- fused stats + BN + lrelu + max over n -> gmax (fp32 Kahan) ----------------
__global__ void k_stats_gmax(const float* __restrict__ buf,
                             const float* __restrict__ gamma, const float* __restrict__ beta) {
    int o = blockIdx.x;  // 512
    float s = 0.f, sc = 0.f, s2 = 0.f, s2c = 0.f;
    for (int i = threadIdx.x; i < Bsz * Npt; i += 256) {
        int b = i >> 12, n = i & (Npt - 1);
        float v = buf[((long)b * 512 + o) * Npt + n];
        kadd(s, sc, v);
        kadd(s2, s2c, v * v);
    }
    __shared__ float sh[256], sh2[256];
    __shared__ float smv, srv;
    sh[threadIdx.x] = s; sh2[threadIdx.x] = s2; __syncthreads();
    for (int st = 128; st > 0; st >>= 1) {
        if (threadIdx.x < st) { sh[threadIdx.x] += sh[threadIdx.x + st]; sh2[threadIdx.x] += sh2[threadIdx.x + st]; }
        __syncthreads();
    }
    if (threadIdx.x == 0) {
        float cnt = (float)(Bsz * Npt);
        float m = sh[0] / cnt;
        float var = sh2[0] / cnt - m * m;
        smv = m;
        srv = rsqrtf(fmaxf(var, 0.f) + EPSBN);
    }
    __syncthreads();
    float m = smv, r = srv, g = gamma[o], be = beta[o];
    __shared__ float shm[256];
    for (int b = 0; b < Bsz; b++) {
        float best = -FLT_MAX;
        for (int n = threadIdx.x; n < Npt; n += 256) {
            float v = buf[((long)b * 512 + o) * Npt + n];
            best = fmaxf(best, lrelu((v - m) * r * g + be));
        }
        shm[threadIdx.x] = best; __syncthreads();
        for (int st = 128; st > 0; st >>= 1) {
            if (threadIdx.x < st) shm[threadIdx.x] = fmaxf(shm[threadIdx.x], shm[threadIdx.x + st]);
            __syncthreads();
        }
        if (threadIdx.x == 0) d_gmax[b * 512 + o] = shm[0];
        __syncthreads();
    }
}

// ---------------- fold W5[:,192:] @ broadcast(gmax) into a per-(b,o) bias ----------------
__global__ void k_bias5(const float* __restrict__ W5) {
    int t = blockIdx.x * 128 + threadIdx.x;
    int b = t >> 9, o = t & 511;
    float s = 0.f;
    #pragma unroll 8
    for (int c = 0; c < 512; c++)
        s += W5[(long)o * 704 + 192 + c] * d_gmax[b * 512 + c];
    d_bias5[b * 512 + o] = s;
}

// ---------------- final conv 128 -> 2 + bias ----------------
__global__ void k_final(const float* __restrict__ W8, const float* __restrict__ b8,
                        float* __restrict__ out) {
    int n = blockIdx.x * 256 + threadIdx.x, b = blockIdx.y;
    float s0 = b8[0], s1 = b8[1];
    #pragma unroll 8
    for (int c = 0; c < 128; c++) {
        float h = d_y7[((long)b * 128 + c) * Npt + n];
        s0 += W8[c] * h;
        s1 += W8[128 + c] * h;
    }
    out[(b * 2 + 0) * Npt + n] = s0;
    out[(b * 2 + 1) * Npt + n] = s1;
}

// ---------------- host ----------------
extern "C" void kernel_launch(void* const* d_in, const int* in_sizes, int n_in,
                              void* d_out, int out_size) {
    (void)in_sizes; (void)n_in; (void)out_size;
    const float* x   = (const float*)d_in[0];
    const float* W1  = (const float*)d_in[1];
    const float* W2  = (const float*)d_in[2];
    const float* W3  = (const float*)d_in[3];
    const float* W4  = (const float*)d_in[4];
    const float* W5  = (const float*)d_in[5];
    const float* W6  = (const float*)d_in[6];
    const float* W7  = (const float*)d_in[7];
    const float* W8  = (const float*)d_in[8];
    const float* b8  = (const float*)d_in[9];
    const float* g1 = (const float*)d_in[10], *bb1 = (const float*)d_in[11];
    const float* g2 = (const float*)d_in[12], *bb2 = (const float*)d_in[13];
    const float* g3 = (const float*)d_in[14], *bb3 = (const float*)d_in[15];
    const float* g4 = (const float*)d_in[16], *bb4 = (const float*)d_in[17];
    const float* g5 = (const float*)d_in[18], *bb5 = (const float*)d_in[19];
    const float* g6 = (const float*)d_in[20], *bb6 = (const float*)d_in[21];
    const float* g7 = (const float*)d_in[22], *bb7 = (const float*)d_in[23];

    void *pv;
    cudaGetSymbolAddress(&pv, d_xcat);  float* p_xcat = (float*)pv;
    cudaGetSymbolAddress(&pv, d_AC);    float* p_AC   = (float*)pv;
    cudaGetSymbolAddress(&pv, d_y4);    float* p_y4   = (float*)pv;
    cudaGetSymbolAddress(&pv, d_y5);    float* p_y5   = (float*)pv;
    cudaGetSymbolAddress(&pv, d_y6);    float* p_y6   = (float*)pv;
    cudaGetSymbolAddress(&pv, d_y7);    float* p_y7   = (float*)pv;
    cudaGetSymbolAddress(&pv, d_bias5); float* p_b5   = (float*)pv;

    // conv1 + BN + lrelu -> x1 (xcat[0:64))
    k_conv1<<<dim3(16, 64, 4), 256>>>(x, W1);
    k_statsapply<<<64, 256>>>(p_xcat, 192, 0, g1, bb1);

    // kNN round 1 on x1: symmetric dist + group max -> fused select
    k_dist_sym<<<dim3(32, 32, 4), 256>>>(0);
    k_knn_select<<<2048, 256>>>();

    // edge-conv 2 -> x2 (xcat[64:128))
    k_gemm_edge<<<dim3(32, 1, 4), 256>>>(p_AC, p_xcat, W2, 0);
    k_edge_stats_part<<<dim3(64, 8), 256>>>();
    k_edge_apply<<<dim3(16, 64, 4), 256>>>(g2, bb2, 64);

    // kNN round 2 on x2
    k_dist_sym<<<dim3(32, 32, 4), 256>>>(64);
    k_knn_select<<<2048, 256>>>();

    // edge-conv 3 -> x3 (xcat[128:192))
    k_gemm_edge<<<dim3(32, 1, 4), 256>>>(p_AC, p_xcat, W3, 64);
    k_edge_stats_part<<<dim3(64, 8), 256>>>();
    k_edge_apply<<<dim3(16, 64, 4), 256>>>(g3, bb3, 128);

    // global branch: y4 = W4 @ x3; fused stats+BN+lrelu+max -> gmax; fold into bias5
    k_gemm128<<<dim3(32, 4, 4), 256>>>(p_y4, p_xcat, W4, nullptr, 64, 64, 192, 128, 512, 0);
    k_stats_gmax<<<512, 256>>>(p_y4, g4, bb4);
    k_bias5<<<16, 128>>>(W5);

    // W5 on [x1;x2;x3] (C=192) + bias5; BN; lrelu
    k_gemm128<<<dim3(32, 4, 4), 256>>>(p_y5, p_xcat, W5, p_b5, 192, 704, 192, 0, 512, 0);
    k_statsapply<<<512, 256>>>(p_y5, 512, 0, g5, bb5);

    // W6
    k_gemm128<<<dim3(32, 2, 4), 256>>>(p_y6, p_y5, W6, nullptr, 512, 512, 512, 0, 256, 0);
    k_statsapply<<<256, 256>>>(p_y6, 256, 0, g6, bb6);

    // W7
    k_gemm128<<<dim3(32, 1, 4), 256>>>(p_y7, p_y6, W7, nullptr, 256, 256, 256, 0, 128, 0);
    k_statsapply<<<128, 256>>>(p_y7, 128, 0, g7, bb7);

    // final 128 -> 2
    k_final<<<dim3(16, 4), 256>>>(W8, b8, (float*)d_out);
}